// round 5
// baseline (speedup 1.0000x reference)
#include <cuda_runtime.h>
#include <cuda_bf16.h>
#include <cstdint>
#include <math.h>

#define SEQ     1024
#define INPUT_D 512
#define HID     1024
#define GATES_N 4096
#define STEPS   128
#define OUT_D   1000

// ---------------- device scratch (no cudaMalloc allowed) ----------------
__device__ __nv_bfloat16 g_xhi[(size_t)STEPS * SEQ * INPUT_D];
__device__ __nv_bfloat16 g_xlo[(size_t)STEPS * SEQ * INPUT_D];
__device__ __nv_bfloat16 g_wxh[2][GATES_N * INPUT_D];   // permuted (gate-interleaved rows)
__device__ __nv_bfloat16 g_wxl[2][GATES_N * INPUT_D];
__device__ __nv_bfloat16 g_whh[2][GATES_N * HID];
__device__ __nv_bfloat16 g_whl[2][GATES_N * HID];
__device__ float g_bias[2][GATES_N];                     // permuted b_ih + b_hh
__device__ __nv_bfloat16 g_hhi[2][SEQ * HID];            // double-buffered h
__device__ __nv_bfloat16 g_hlo[2][SEQ * HID];
__device__ float g_c[SEQ * HID];
__device__ float g_hlast[STEPS * HID];

// ---------------- helpers ----------------
__device__ __forceinline__ uint32_t smem_u32(const void* p) {
    return (uint32_t)__cvta_generic_to_shared(p);
}
__device__ __forceinline__ void cp16(uint32_t saddr, const void* gaddr) {
    asm volatile("cp.async.cg.shared.global [%0], [%1], 16;" :: "r"(saddr), "l"(gaddr) : "memory");
}
#define CP_COMMIT() asm volatile("cp.async.commit_group;" ::: "memory")
#define CP_WAIT(n)  asm volatile("cp.async.wait_group %0;" :: "n"(n) : "memory")

__device__ __forceinline__ uint32_t sw128(uint32_t off) {
    return off ^ ((off >> 3) & 0x70);
}

// ---------------- fused GEMM + LSTM cell ----------------
// gates[m][n] (gate-interleaved n) = sum over 72 chunks (3 bf16 products x K=1536)
// then the epilogue computes c/h in-kernel.
#define TILE_M   128
#define TILE_N   256
#define CHUNK_K  64
#define NS       4
#define NCHUNKS  72
#define A_BYTES  (TILE_M * CHUNK_K * 2)          // 16 KB
#define B_BYTES  (TILE_N * CHUNK_K * 2)          // 32 KB
#define STAGE_BYTES (A_BYTES + B_BYTES)          // 48 KB
#define SMEM_DYN (NS * STAGE_BYTES)              // 192 KB

__global__ __launch_bounds__(256, 1)
void gemm_lstm_fused(const __nv_bfloat16* __restrict__ xhi, const __nv_bfloat16* __restrict__ xlo,
                     const __nv_bfloat16* __restrict__ hhi, const __nv_bfloat16* __restrict__ hlo,
                     const __nv_bfloat16* __restrict__ wxh, const __nv_bfloat16* __restrict__ wxl,
                     const __nv_bfloat16* __restrict__ whh, const __nv_bfloat16* __restrict__ whl,
                     const float* __restrict__ bsum,
                     float* __restrict__ c,
                     __nv_bfloat16* __restrict__ hhi_w, __nv_bfloat16* __restrict__ hlo_w,
                     float* __restrict__ hlast)
{
    extern __shared__ __align__(1024) char smem_raw[];
    const uint32_t sbase = smem_u32(smem_raw);

    const int tid = threadIdx.x;
    const int wid = tid >> 5;
    const int lane = tid & 31;
    const int wm = wid & 1;          // 2 warps along M (64 rows)
    const int wn = wid >> 1;         // 4 warps along N (64 cols)
    const int bn = blockIdx.x * TILE_N;
    const int bm = blockIdx.y * TILE_M;

    auto get_src = [&](int cc, const __nv_bfloat16*& a, const __nv_bfloat16*& b,
                       int& k0, int& kst) {
        const int prod = cc / 24;      // 0: hi*hi, 1: hi*lo, 2: lo*hi
        const int r = cc - prod * 24;
        if (r < 8) {                   // x-part, K=512
            kst = INPUT_D; k0 = r * CHUNK_K;
            a = (prod == 2) ? xlo : xhi;
            b = (prod == 1) ? wxl : wxh;
        } else {                       // h-part, K=1024
            kst = HID; k0 = (r - 8) * CHUNK_K;
            a = (prod == 2) ? hlo : hhi;
            b = (prod == 1) ? whl : whh;
        }
    };

    auto load_chunk = [&](int cc, int stage) {
        const __nv_bfloat16 *a, *b; int k0, kst;
        get_src(cc, a, b, k0, kst);
        const uint32_t abase = sbase + stage * STAGE_BYTES;
        const uint32_t bbase = abase + A_BYTES;
#pragma unroll
        for (int v = 0; v < 4; v++) {                 // A: 128x64 -> 1024 vec16
            const int idx = v * 256 + tid;
            const int row = idx >> 3, c16 = idx & 7;
            cp16(abase + sw128(row * 128 + c16 * 16),
                 a + (size_t)(bm + row) * kst + k0 + c16 * 8);
        }
#pragma unroll
        for (int v = 0; v < 8; v++) {                 // B: 256x64 -> 2048 vec16
            const int idx = v * 256 + tid;
            const int row = idx >> 3, c16 = idx & 7;
            cp16(bbase + sw128(row * 128 + c16 * 16),
                 b + (size_t)(bn + row) * kst + k0 + c16 * 8);
        }
    };

    float acc[4][8][4];
#pragma unroll
    for (int i = 0; i < 4; i++)
#pragma unroll
        for (int j = 0; j < 8; j++)
#pragma unroll
            for (int q = 0; q < 4; q++) acc[i][j][q] = 0.0f;

    auto compute_chunk = [&](int stage) {
        const uint32_t abase = sbase + stage * STAGE_BYTES;
        const uint32_t bbase = abase + A_BYTES;
#pragma unroll
        for (int ks = 0; ks < 4; ks++) {
            uint32_t bf[8][2];
#pragma unroll
            for (int ntp = 0; ntp < 4; ntp++) {
                const int g = lane >> 3, l7 = lane & 7;
                const int nrow = wn * 64 + ntp * 16 + ((g >> 1) << 3) + l7;
                const uint32_t addr = bbase + sw128(nrow * 128 + ks * 32 + (g & 1) * 16);
                asm volatile("ldmatrix.sync.aligned.m8n8.x4.shared.b16 {%0,%1,%2,%3}, [%4];"
                    : "=r"(bf[ntp * 2][0]), "=r"(bf[ntp * 2][1]),
                      "=r"(bf[ntp * 2 + 1][0]), "=r"(bf[ntp * 2 + 1][1])
                    : "r"(addr));
            }
#pragma unroll
            for (int mt = 0; mt < 4; mt++) {
                const int mrow = wm * 64 + mt * 16 + (lane & 15);
                const uint32_t aaddr = abase + sw128(mrow * 128 + ks * 32 + (lane >> 4) * 16);
                uint32_t a0, a1, a2, a3;
                asm volatile("ldmatrix.sync.aligned.m8n8.x4.shared.b16 {%0,%1,%2,%3}, [%4];"
                    : "=r"(a0), "=r"(a1), "=r"(a2), "=r"(a3) : "r"(aaddr));
#pragma unroll
                for (int nt = 0; nt < 8; nt++) {
                    asm volatile(
                        "mma.sync.aligned.m16n8k16.row.col.f32.bf16.bf16.f32 "
                        "{%0,%1,%2,%3}, {%4,%5,%6,%7}, {%8,%9}, {%0,%1,%2,%3};"
                        : "+f"(acc[mt][nt][0]), "+f"(acc[mt][nt][1]),
                          "+f"(acc[mt][nt][2]), "+f"(acc[mt][nt][3])
                        : "r"(a0), "r"(a1), "r"(a2), "r"(a3),
                          "r"(bf[nt][0]), "r"(bf[nt][1]));
                }
            }
        }
    };

    // prologue: stages 0..NS-2
#pragma unroll
    for (int p = 0; p < NS - 1; p++) { load_chunk(p, p); CP_COMMIT(); }

#pragma unroll 1
    for (int i = 0; i < NCHUNKS; i++) {
        CP_WAIT(NS - 2);          // chunk i resident
        __syncthreads();          // all warps done with stage being overwritten
        if (i + NS - 1 < NCHUNKS) load_chunk(i + NS - 1, (i + NS - 1) % NS);
        CP_COMMIT();
        compute_chunk(i % NS);
    }

    // ---------------- fused epilogue: bias + LSTM cell ----------------
    // col n (gate-interleaved): unit u = n>>2, gate = n&3.
    // Thread cols per (mt,nt): n0 = bn + wn*64 + nt*8 + (lane&3)*2, n0+1.
    // lane&3 even -> (i,f) of a unit; odd -> (g,o) of the same unit.
#pragma unroll
    for (int mt = 0; mt < 4; mt++)
#pragma unroll
        for (int nt = 0; nt < 8; nt++) {
            const int n0 = bn + wn * 64 + nt * 8 + (lane & 3) * 2;
            const float bs0 = bsum[n0];
            const float bs1 = bsum[n0 + 1];
            acc[mt][nt][0] += bs0; acc[mt][nt][1] += bs1;
            acc[mt][nt][2] += bs0; acc[mt][nt][3] += bs1;
        }

    const unsigned FULL = 0xFFFFFFFFu;
    const bool evenlane = ((lane & 1) == 0);
#pragma unroll
    for (int mt = 0; mt < 4; mt++) {
        const int m0 = bm + wm * 64 + mt * 16 + (lane >> 2);
        const int m = evenlane ? m0 : (m0 + 8);
#pragma unroll
        for (int nt = 0; nt < 8; nt++) {
            const int u = (bn >> 2) + wn * 16 + nt * 2 + ((lane & 3) >> 1);
            // exchange gate pairs with partner lane (lane^1)
            const float p0 = __shfl_xor_sync(FULL, acc[mt][nt][0], 1);
            const float p1 = __shfl_xor_sync(FULL, acc[mt][nt][1], 1);
            const float p2 = __shfl_xor_sync(FULL, acc[mt][nt][2], 1);
            const float p3 = __shfl_xor_sync(FULL, acc[mt][nt][3], 1);
            float gi, gf, gg, go;
            if (evenlane) { gi = acc[mt][nt][0]; gf = acc[mt][nt][1]; gg = p0; go = p1; }
            else          { gi = p2;             gf = p3;             gg = acc[mt][nt][2]; go = acc[mt][nt][3]; }

            const int idx = m * HID + u;
            const float co = c[idx];
            const float si = 1.0f / (1.0f + expf(-gi));
            const float sf = 1.0f / (1.0f + expf(-gf));
            const float so = 1.0f / (1.0f + expf(-go));
            const float tg = tanhf(gg);
            const float cn = sf * co + si * tg;
            const float hn = so * tanhf(cn);
            c[idx] = cn;
            const __nv_bfloat16 hh = __float2bfloat16(hn);
            hhi_w[idx] = hh;
            hlo_w[idx] = __float2bfloat16(hn - __bfloat162float(hh));
            if (hlast != nullptr && m == SEQ - 1) hlast[u] = hn;
        }
    }
}

// ---------------- setup kernels ----------------
__global__ void split_kernel(const float* __restrict__ src, __nv_bfloat16* __restrict__ hi,
                             __nv_bfloat16* __restrict__ lo, size_t n, float scale)
{
    const size_t i = (size_t)blockIdx.x * blockDim.x + threadIdx.x;
    if (i < n) {
        const float v = src[i] * scale;
        const __nv_bfloat16 h = __float2bfloat16(v);
        hi[i] = h;
        lo[i] = __float2bfloat16(v - __bfloat162float(h));
    }
}

// permute rows to gate-interleaved order: new_row = 4*unit + gate
__global__ void split_permute_w(const float* __restrict__ src, __nv_bfloat16* __restrict__ hi,
                                __nv_bfloat16* __restrict__ lo, int kshift)
{
    const size_t i = (size_t)blockIdx.x * blockDim.x + threadIdx.x;
    const int K = 1 << kshift;
    if (i < (size_t)GATES_N << kshift) {
        const int row = (int)(i >> kshift);
        const int k = (int)(i & (K - 1));
        const int nrow = ((row & 1023) << 2) | (row >> 10);
        const float v = src[i];
        const __nv_bfloat16 h = __float2bfloat16(v);
        hi[(size_t)nrow * K + k] = h;
        lo[(size_t)nrow * K + k] = __float2bfloat16(v - __bfloat162float(h));
    }
}

__global__ void bias_combine(const float* __restrict__ b_ih, const float* __restrict__ b_hh,
                             float* __restrict__ bsum)
{
    const int i = blockIdx.x * blockDim.x + threadIdx.x;
    if (i < GATES_N) {
        const int ni = ((i & 1023) << 2) | (i >> 10);
        bsum[ni] = b_ih[i] + b_hh[i];
    }
}

__global__ void zero_state_kernel()
{
    const int i = blockIdx.x * blockDim.x + threadIdx.x;
    if (i < SEQ * HID) {
        g_hhi[0][i] = __float2bfloat16(0.f);
        g_hlo[0][i] = __float2bfloat16(0.f);
        g_hhi[1][i] = __float2bfloat16(0.f);
        g_hlo[1][i] = __float2bfloat16(0.f);
        g_c[i] = 0.f;
    }
}

__global__ __launch_bounds__(256)
void fc_kernel(const float* __restrict__ Hl, const float* __restrict__ Wfc,
               const float* __restrict__ bfc, float* __restrict__ out)
{
    __shared__ float hrow[HID];
    const int t = blockIdx.x;
    for (int k = threadIdx.x; k < HID; k += 256) hrow[k] = Hl[(size_t)t * HID + k];
    __syncthreads();
    for (int n = threadIdx.x; n < OUT_D; n += 256) {
        const float* w = Wfc + (size_t)n * HID;
        float s = 0.f;
#pragma unroll 8
        for (int k = 0; k < HID; k++) s = fmaf(hrow[k], w[k], s);
        out[(size_t)t * OUT_D + n] = s + bfc[n];
    }
}

// ---------------- launch ----------------
extern "C" void kernel_launch(void* const* d_in, const int* in_sizes, int n_in,
                              void* d_out, int out_size)
{
    const float* x     = (const float*)d_in[0];
    const float* w_ih1 = (const float*)d_in[1];
    const float* w_hh1 = (const float*)d_in[2];
    const float* b_ih1 = (const float*)d_in[3];
    const float* b_hh1 = (const float*)d_in[4];
    const float* w_ih2 = (const float*)d_in[5];
    const float* w_hh2 = (const float*)d_in[6];
    const float* b_ih2 = (const float*)d_in[7];
    const float* b_hh2 = (const float*)d_in[8];
    const float* w_fc  = (const float*)d_in[9];
    const float* b_fc  = (const float*)d_in[10];
    float* out = (float*)d_out;

    __nv_bfloat16 *xhi, *xlo, *wxh, *wxl, *whh, *whl, *hhi, *hlo;
    float *c, *hlast, *bias;
    cudaGetSymbolAddress((void**)&xhi, g_xhi);
    cudaGetSymbolAddress((void**)&xlo, g_xlo);
    cudaGetSymbolAddress((void**)&wxh, g_wxh);
    cudaGetSymbolAddress((void**)&wxl, g_wxl);
    cudaGetSymbolAddress((void**)&whh, g_whh);
    cudaGetSymbolAddress((void**)&whl, g_whl);
    cudaGetSymbolAddress((void**)&hhi, g_hhi);
    cudaGetSymbolAddress((void**)&hlo, g_hlo);
    cudaGetSymbolAddress((void**)&c,     g_c);
    cudaGetSymbolAddress((void**)&hlast, g_hlast);
    cudaGetSymbolAddress((void**)&bias,  g_bias);

    cudaFuncSetAttribute(gemm_lstm_fused, cudaFuncAttributeMaxDynamicSharedMemorySize, SMEM_DYN);

    const size_t nwx = (size_t)GATES_N * INPUT_D;
    const size_t nwh = (size_t)GATES_N * HID;

    // setup: split x (*255), permute+split weights, combine+permute biases
    {
        const size_t nx = (size_t)STEPS * SEQ * INPUT_D;
        split_kernel<<<(unsigned)((nx + 255) / 256), 256>>>(x, xhi, xlo, nx, 255.0f);
        split_permute_w<<<(unsigned)((nwx + 255) / 256), 256>>>(w_ih1, wxh, wxl, 9);
        split_permute_w<<<(unsigned)((nwh + 255) / 256), 256>>>(w_hh1, whh, whl, 10);
        split_permute_w<<<(unsigned)((nwx + 255) / 256), 256>>>(w_ih2, wxh + nwx, wxl + nwx, 9);
        split_permute_w<<<(unsigned)((nwh + 255) / 256), 256>>>(w_hh2, whh + nwh, whl + nwh, 10);
        bias_combine<<<(GATES_N + 255) / 256, 256>>>(b_ih1, b_hh1, bias);
        bias_combine<<<(GATES_N + 255) / 256, 256>>>(b_ih2, b_hh2, bias + GATES_N);
    }
    zero_state_kernel<<<(SEQ * HID + 255) / 256, 256>>>();

    const dim3 ggrid(GATES_N / TILE_N, SEQ / TILE_M);   // (16, 8) = 128 CTAs
    int p = 0;
    for (int t = 0; t < STEPS; ++t) {
        const __nv_bfloat16* xth = xhi + (size_t)t * SEQ * INPUT_D;
        const __nv_bfloat16* xtl = xlo + (size_t)t * SEQ * INPUT_D;

        gemm_lstm_fused<<<ggrid, 256, SMEM_DYN>>>(
            xth, xtl, hhi + (size_t)p * SEQ * HID, hlo + (size_t)p * SEQ * HID,
            wxh, wxl, whh, whl, bias, c,
            hhi + (size_t)(1 - p) * SEQ * HID, hlo + (size_t)(1 - p) * SEQ * HID,
            nullptr);
        p ^= 1;

        gemm_lstm_fused<<<ggrid, 256, SMEM_DYN>>>(
            xth, xtl, hhi + (size_t)p * SEQ * HID, hlo + (size_t)p * SEQ * HID,
            wxh + nwx, wxl + nwx, whh + nwh, whl + nwh, bias + GATES_N, c,
            hhi + (size_t)(1 - p) * SEQ * HID, hlo + (size_t)(1 - p) * SEQ * HID,
            hlast + (size_t)t * HID);
        p ^= 1;
    }

    fc_kernel<<<STEPS, 256>>>(hlast, w_fc, b_fc, out);
}

// round 6
// speedup vs baseline: 1.0123x; 1.0123x over previous
#include <cuda_runtime.h>
#include <cuda_bf16.h>
#include <cstdint>
#include <math.h>

#define SEQ     1024
#define INPUT_D 512
#define HID     1024
#define GATES_N 4096
#define STEPS   128
#define OUT_D   1000

// ---------------- device scratch (no cudaMalloc allowed) ----------------
__device__ __nv_bfloat16 g_xhi[(size_t)STEPS * SEQ * INPUT_D];
__device__ __nv_bfloat16 g_xlo[(size_t)STEPS * SEQ * INPUT_D];
__device__ __nv_bfloat16 g_wxh[2][GATES_N * INPUT_D];   // permuted (gate-interleaved rows)
__device__ __nv_bfloat16 g_wxl[2][GATES_N * INPUT_D];
__device__ __nv_bfloat16 g_whh[2][GATES_N * HID];
__device__ __nv_bfloat16 g_whl[2][GATES_N * HID];
__device__ float g_bias[2][GATES_N];                     // permuted b_ih + b_hh
__device__ __nv_bfloat16 g_hhi[2][SEQ * HID];            // double-buffered h
__device__ __nv_bfloat16 g_hlo[2][SEQ * HID];
__device__ float g_c[SEQ * HID];
__device__ float g_hlast[STEPS * HID];

// ---------------- helpers ----------------
__device__ __forceinline__ uint32_t smem_u32(const void* p) {
    return (uint32_t)__cvta_generic_to_shared(p);
}
__device__ __forceinline__ void cp16(uint32_t saddr, const void* gaddr) {
    asm volatile("cp.async.cg.shared.global [%0], [%1], 16;" :: "r"(saddr), "l"(gaddr) : "memory");
}
#define CP_COMMIT() asm volatile("cp.async.commit_group;" ::: "memory")
#define CP_WAIT(n)  asm volatile("cp.async.wait_group %0;" :: "n"(n) : "memory")

__device__ __forceinline__ uint32_t sw128(uint32_t off) {
    return off ^ ((off >> 3) & 0x70);
}

// ---------------- fused GEMM + LSTM cell (R4 tile config + fused epilogue) ----
#define TILE_M   128
#define TILE_N   128
#define CHUNK_K  64
#define NS       3
#define NCHUNKS  72
#define A_BYTES  (TILE_M * CHUNK_K * 2)      // 16 KB
#define STAGE_BYTES (2 * A_BYTES)            // 32 KB
#define SMEM_DYN (NS * STAGE_BYTES)          // 96 KB -> 2 CTAs/SM

__global__ __launch_bounds__(256, 2)
void gemm_lstm_fused(const __nv_bfloat16* __restrict__ xhi, const __nv_bfloat16* __restrict__ xlo,
                     const __nv_bfloat16* __restrict__ hhi, const __nv_bfloat16* __restrict__ hlo,
                     const __nv_bfloat16* __restrict__ wxh, const __nv_bfloat16* __restrict__ wxl,
                     const __nv_bfloat16* __restrict__ whh, const __nv_bfloat16* __restrict__ whl,
                     const float* __restrict__ bsum,
                     float* __restrict__ c,
                     __nv_bfloat16* __restrict__ hhi_w, __nv_bfloat16* __restrict__ hlo_w,
                     float* __restrict__ hlast)
{
    extern __shared__ __align__(1024) char smem_raw[];
    const uint32_t sbase = smem_u32(smem_raw);

    const int tid = threadIdx.x;
    const int wid = tid >> 5;
    const int lane = tid & 31;
    const int wm = wid & 1;          // 2 warps along M (64 rows each)
    const int wn = wid >> 1;         // 4 warps along N (32 cols each)
    const int bn = blockIdx.x * TILE_N;
    const int bm = blockIdx.y * TILE_M;

    auto get_src = [&](int cc, const __nv_bfloat16*& a, const __nv_bfloat16*& b,
                       int& k0, int& kst) {
        const int prod = cc / 24;      // 0: hi*hi, 1: hi*lo, 2: lo*hi
        const int r = cc - prod * 24;
        if (r < 8) {                   // x-part, K=512
            kst = INPUT_D; k0 = r * CHUNK_K;
            a = (prod == 2) ? xlo : xhi;
            b = (prod == 1) ? wxl : wxh;
        } else {                       // h-part, K=1024
            kst = HID; k0 = (r - 8) * CHUNK_K;
            a = (prod == 2) ? hlo : hhi;
            b = (prod == 1) ? whl : whh;
        }
    };

    const int lrow = tid >> 3;            // 0..31
    const int lcol = (tid & 7) * 16;      // 16B block within 128B row
    auto load_chunk = [&](int cc, int stage) {
        const __nv_bfloat16 *a, *b; int k0, kst;
        get_src(cc, a, b, k0, kst);
        const uint32_t abase = sbase + stage * STAGE_BYTES;
        const uint32_t bbase = abase + A_BYTES;
#pragma unroll
        for (int v = 0; v < 4; v++) {
            const int row = v * 32 + lrow;
            cp16(abase + sw128(row * 128 + lcol),
                 a + (size_t)(bm + row) * kst + k0 + lcol / 2);
            cp16(bbase + sw128(row * 128 + lcol),
                 b + (size_t)(bn + row) * kst + k0 + lcol / 2);
        }
    };

    float acc[4][4][4];
#pragma unroll
    for (int i = 0; i < 4; i++)
#pragma unroll
        for (int j = 0; j < 4; j++)
#pragma unroll
            for (int q = 0; q < 4; q++) acc[i][j][q] = 0.0f;

    auto compute_chunk = [&](int stage) {
        const uint32_t abase = sbase + stage * STAGE_BYTES;
        const uint32_t bbase = abase + A_BYTES;
#pragma unroll
        for (int ks = 0; ks < 4; ks++) {
            uint32_t bf[4][2];
#pragma unroll
            for (int ntp = 0; ntp < 2; ntp++) {
                const int g = lane >> 3, l7 = lane & 7;
                const int nrow = wn * 32 + ntp * 16 + ((g >> 1) << 3) + l7;
                const uint32_t addr = bbase + sw128(nrow * 128 + ks * 32 + (g & 1) * 16);
                asm volatile("ldmatrix.sync.aligned.m8n8.x4.shared.b16 {%0,%1,%2,%3}, [%4];"
                    : "=r"(bf[ntp * 2][0]), "=r"(bf[ntp * 2][1]),
                      "=r"(bf[ntp * 2 + 1][0]), "=r"(bf[ntp * 2 + 1][1])
                    : "r"(addr));
            }
#pragma unroll
            for (int mt = 0; mt < 4; mt++) {
                const int mrow = wm * 64 + mt * 16 + (lane & 15);
                const uint32_t aaddr = abase + sw128(mrow * 128 + ks * 32 + (lane >> 4) * 16);
                uint32_t a0, a1, a2, a3;
                asm volatile("ldmatrix.sync.aligned.m8n8.x4.shared.b16 {%0,%1,%2,%3}, [%4];"
                    : "=r"(a0), "=r"(a1), "=r"(a2), "=r"(a3) : "r"(aaddr));
#pragma unroll
                for (int nt = 0; nt < 4; nt++) {
                    asm volatile(
                        "mma.sync.aligned.m16n8k16.row.col.f32.bf16.bf16.f32 "
                        "{%0,%1,%2,%3}, {%4,%5,%6,%7}, {%8,%9}, {%0,%1,%2,%3};"
                        : "+f"(acc[mt][nt][0]), "+f"(acc[mt][nt][1]),
                          "+f"(acc[mt][nt][2]), "+f"(acc[mt][nt][3])
                        : "r"(a0), "r"(a1), "r"(a2), "r"(a3),
                          "r"(bf[nt][0]), "r"(bf[nt][1]));
                }
            }
        }
    };

    // prologue
#pragma unroll
    for (int p = 0; p < NS - 1; p++) { load_chunk(p, p); CP_COMMIT(); }

#pragma unroll 1
    for (int i = 0; i < NCHUNKS; i++) {
        CP_WAIT(NS - 2);
        __syncthreads();
        if (i + NS - 1 < NCHUNKS) load_chunk(i + NS - 1, (i + NS - 1) % NS);
        CP_COMMIT();
        compute_chunk(i % NS);
    }

    // ---------------- fused epilogue: bias + LSTM cell ----------------
    // gate-interleaved col n: unit u = n>>2, gate = n&3.
#pragma unroll
    for (int mt = 0; mt < 4; mt++)
#pragma unroll
        for (int nt = 0; nt < 4; nt++) {
            const int n0 = bn + wn * 32 + nt * 8 + (lane & 3) * 2;
            const float bs0 = bsum[n0];
            const float bs1 = bsum[n0 + 1];
            acc[mt][nt][0] += bs0; acc[mt][nt][1] += bs1;
            acc[mt][nt][2] += bs0; acc[mt][nt][3] += bs1;
        }

    const unsigned FULL = 0xFFFFFFFFu;
    const bool evenlane = ((lane & 1) == 0);
#pragma unroll
    for (int mt = 0; mt < 4; mt++) {
        const int m0 = bm + wm * 64 + mt * 16 + (lane >> 2);
        const int m = evenlane ? m0 : (m0 + 8);
#pragma unroll
        for (int nt = 0; nt < 4; nt++) {
            const int u = (bn >> 2) + wn * 8 + nt * 2 + ((lane & 3) >> 1);
            const float p0 = __shfl_xor_sync(FULL, acc[mt][nt][0], 1);
            const float p1 = __shfl_xor_sync(FULL, acc[mt][nt][1], 1);
            const float p2 = __shfl_xor_sync(FULL, acc[mt][nt][2], 1);
            const float p3 = __shfl_xor_sync(FULL, acc[mt][nt][3], 1);
            float gi, gf, gg, go;
            if (evenlane) { gi = acc[mt][nt][0]; gf = acc[mt][nt][1]; gg = p0; go = p1; }
            else          { gi = p2;             gf = p3;             gg = acc[mt][nt][2]; go = acc[mt][nt][3]; }

            const int idx = m * HID + u;
            const float co = c[idx];
            const float si = 1.0f / (1.0f + expf(-gi));
            const float sf = 1.0f / (1.0f + expf(-gf));
            const float so = 1.0f / (1.0f + expf(-go));
            const float tg = tanhf(gg);
            const float cn = sf * co + si * tg;
            const float hn = so * tanhf(cn);
            c[idx] = cn;
            const __nv_bfloat16 hh = __float2bfloat16(hn);
            hhi_w[idx] = hh;
            hlo_w[idx] = __float2bfloat16(hn - __bfloat162float(hh));
            if (hlast != nullptr && m == SEQ - 1) hlast[u] = hn;
        }
    }
}

// ---------------- setup kernels ----------------
__global__ void split_kernel(const float* __restrict__ src, __nv_bfloat16* __restrict__ hi,
                             __nv_bfloat16* __restrict__ lo, size_t n, float scale)
{
    const size_t i = (size_t)blockIdx.x * blockDim.x + threadIdx.x;
    if (i < n) {
        const float v = src[i] * scale;
        const __nv_bfloat16 h = __float2bfloat16(v);
        hi[i] = h;
        lo[i] = __float2bfloat16(v - __bfloat162float(h));
    }
}

// permute rows to gate-interleaved order: new_row = 4*unit + gate
__global__ void split_permute_w(const float* __restrict__ src, __nv_bfloat16* __restrict__ hi,
                                __nv_bfloat16* __restrict__ lo, int kshift)
{
    const size_t i = (size_t)blockIdx.x * blockDim.x + threadIdx.x;
    const int K = 1 << kshift;
    if (i < (size_t)GATES_N << kshift) {
        const int row = (int)(i >> kshift);
        const int k = (int)(i & (K - 1));
        const int nrow = ((row & 1023) << 2) | (row >> 10);
        const float v = src[i];
        const __nv_bfloat16 h = __float2bfloat16(v);
        hi[(size_t)nrow * K + k] = h;
        lo[(size_t)nrow * K + k] = __float2bfloat16(v - __bfloat162float(h));
    }
}

__global__ void bias_combine(const float* __restrict__ b_ih, const float* __restrict__ b_hh,
                             float* __restrict__ bsum)
{
    const int i = blockIdx.x * blockDim.x + threadIdx.x;
    if (i < GATES_N) {
        const int ni = ((i & 1023) << 2) | (i >> 10);
        bsum[ni] = b_ih[i] + b_hh[i];
    }
}

__global__ void zero_state_kernel()
{
    const int i = blockIdx.x * blockDim.x + threadIdx.x;
    if (i < SEQ * HID) {
        g_hhi[0][i] = __float2bfloat16(0.f);
        g_hlo[0][i] = __float2bfloat16(0.f);
        g_hhi[1][i] = __float2bfloat16(0.f);
        g_hlo[1][i] = __float2bfloat16(0.f);
        g_c[i] = 0.f;
    }
}

__global__ __launch_bounds__(256)
void fc_kernel(const float* __restrict__ Hl, const float* __restrict__ Wfc,
               const float* __restrict__ bfc, float* __restrict__ out)
{
    __shared__ float hrow[HID];
    const int t = blockIdx.x;
    for (int k = threadIdx.x; k < HID; k += 256) hrow[k] = Hl[(size_t)t * HID + k];
    __syncthreads();
    for (int n = threadIdx.x; n < OUT_D; n += 256) {
        const float* w = Wfc + (size_t)n * HID;
        float s = 0.f;
#pragma unroll 8
        for (int k = 0; k < HID; k++) s = fmaf(hrow[k], w[k], s);
        out[(size_t)t * OUT_D + n] = s + bfc[n];
    }
}

// ---------------- launch ----------------
extern "C" void kernel_launch(void* const* d_in, const int* in_sizes, int n_in,
                              void* d_out, int out_size)
{
    const float* x     = (const float*)d_in[0];
    const float* w_ih1 = (const float*)d_in[1];
    const float* w_hh1 = (const float*)d_in[2];
    const float* b_ih1 = (const float*)d_in[3];
    const float* b_hh1 = (const float*)d_in[4];
    const float* w_ih2 = (const float*)d_in[5];
    const float* w_hh2 = (const float*)d_in[6];
    const float* b_ih2 = (const float*)d_in[7];
    const float* b_hh2 = (const float*)d_in[8];
    const float* w_fc  = (const float*)d_in[9];
    const float* b_fc  = (const float*)d_in[10];
    float* out = (float*)d_out;

    __nv_bfloat16 *xhi, *xlo, *wxh, *wxl, *whh, *whl, *hhi, *hlo;
    float *c, *hlast, *bias;
    cudaGetSymbolAddress((void**)&xhi, g_xhi);
    cudaGetSymbolAddress((void**)&xlo, g_xlo);
    cudaGetSymbolAddress((void**)&wxh, g_wxh);
    cudaGetSymbolAddress((void**)&wxl, g_wxl);
    cudaGetSymbolAddress((void**)&whh, g_whh);
    cudaGetSymbolAddress((void**)&whl, g_whl);
    cudaGetSymbolAddress((void**)&hhi, g_hhi);
    cudaGetSymbolAddress((void**)&hlo, g_hlo);
    cudaGetSymbolAddress((void**)&c,     g_c);
    cudaGetSymbolAddress((void**)&hlast, g_hlast);
    cudaGetSymbolAddress((void**)&bias,  g_bias);

    cudaFuncSetAttribute(gemm_lstm_fused, cudaFuncAttributeMaxDynamicSharedMemorySize, SMEM_DYN);

    const size_t nwx = (size_t)GATES_N * INPUT_D;
    const size_t nwh = (size_t)GATES_N * HID;

    // setup: split x (*255), permute+split weights, combine+permute biases
    {
        const size_t nx = (size_t)STEPS * SEQ * INPUT_D;
        split_kernel<<<(unsigned)((nx + 255) / 256), 256>>>(x, xhi, xlo, nx, 255.0f);
        split_permute_w<<<(unsigned)((nwx + 255) / 256), 256>>>(w_ih1, wxh, wxl, 9);
        split_permute_w<<<(unsigned)((nwh + 255) / 256), 256>>>(w_hh1, whh, whl, 10);
        split_permute_w<<<(unsigned)((nwx + 255) / 256), 256>>>(w_ih2, wxh + nwx, wxl + nwx, 9);
        split_permute_w<<<(unsigned)((nwh + 255) / 256), 256>>>(w_hh2, whh + nwh, whl + nwh, 10);
        bias_combine<<<(GATES_N + 255) / 256, 256>>>(b_ih1, b_hh1, bias);
        bias_combine<<<(GATES_N + 255) / 256, 256>>>(b_ih2, b_hh2, bias + GATES_N);
    }
    zero_state_kernel<<<(SEQ * HID + 255) / 256, 256>>>();

    const dim3 ggrid(GATES_N / TILE_N, SEQ / TILE_M);   // (32, 8) = 256 CTAs
    int p = 0;
    for (int t = 0; t < STEPS; ++t) {
        const __nv_bfloat16* xth = xhi + (size_t)t * SEQ * INPUT_D;
        const __nv_bfloat16* xtl = xlo + (size_t)t * SEQ * INPUT_D;

        gemm_lstm_fused<<<ggrid, 256, SMEM_DYN>>>(
            xth, xtl, hhi + (size_t)p * SEQ * HID, hlo + (size_t)p * SEQ * HID,
            wxh, wxl, whh, whl, bias, c,
            hhi + (size_t)(1 - p) * SEQ * HID, hlo + (size_t)(1 - p) * SEQ * HID,
            nullptr);
        p ^= 1;

        gemm_lstm_fused<<<ggrid, 256, SMEM_DYN>>>(
            xth, xtl, hhi + (size_t)p * SEQ * HID, hlo + (size_t)p * SEQ * HID,
            wxh + nwx, wxl + nwx, whh + nwh, whl + nwh, bias + GATES_N, c,
            hhi + (size_t)(1 - p) * SEQ * HID, hlo + (size_t)(1 - p) * SEQ * HID,
            hlast + (size_t)t * HID);
        p ^= 1;
    }

    fc_kernel<<<STEPS, 256>>>(hlast, w_fc, b_fc, out);
}

// round 7
// speedup vs baseline: 1.2647x; 1.2493x over previous
#include <cuda_runtime.h>
#include <cuda_bf16.h>
#include <cstdint>
#include <math.h>

#define SEQ     1024
#define INPUT_D 512
#define HID     1024
#define GATES_N 4096
#define STEPS   128
#define OUT_D   1000

// ---------------- device scratch (no cudaMalloc allowed) ----------------
__device__ __nv_bfloat16 g_xhi[(size_t)STEPS * SEQ * INPUT_D];
__device__ __nv_bfloat16 g_xlo[(size_t)STEPS * SEQ * INPUT_D];
__device__ __nv_bfloat16 g_wxh[2][GATES_N * INPUT_D];   // permuted (gate-interleaved rows)
__device__ __nv_bfloat16 g_wxl[2][GATES_N * INPUT_D];
__device__ __nv_bfloat16 g_whh[2][GATES_N * HID];
__device__ __nv_bfloat16 g_whl[2][GATES_N * HID];
__device__ float g_bias[2][GATES_N];                     // permuted b_ih + b_hh
__device__ __nv_bfloat16 g_hhi[2][SEQ * HID];            // double-buffered h
__device__ __nv_bfloat16 g_hlo[2][SEQ * HID];
__device__ float g_c[SEQ * HID];
__device__ float g_hlast[STEPS * HID];

// ---------------- helpers ----------------
__device__ __forceinline__ uint32_t smem_u32(const void* p) {
    return (uint32_t)__cvta_generic_to_shared(p);
}
__device__ __forceinline__ void cp16(uint32_t saddr, const void* gaddr) {
    asm volatile("cp.async.cg.shared.global [%0], [%1], 16;" :: "r"(saddr), "l"(gaddr) : "memory");
}
#define CP_COMMIT() asm volatile("cp.async.commit_group;" ::: "memory")
#define CP_WAIT(n)  asm volatile("cp.async.wait_group %0;" :: "n"(n) : "memory")

__device__ __forceinline__ uint32_t sw128(uint32_t off) {
    return off ^ ((off >> 3) & 0x70);
}

// ---------------- fused GEMM + LSTM cell, smem-staged coalesced epilogue -----
#define TILE_M   128
#define TILE_N   128
#define CHUNK_K  64
#define NS       3
#define NCHUNKS  72
#define A_BYTES  (TILE_M * CHUNK_K * 2)      // 16 KB
#define STAGE_BYTES (2 * A_BYTES)            // 32 KB
#define SMEM_DYN (NS * STAGE_BYTES)          // 96 KB -> 2 CTAs/SM
#define EPAD     4                            // smem gate-tile row pad (floats)
#define EROW     (TILE_N + EPAD)              // 132 floats per staged row

__global__ __launch_bounds__(256, 2)
void gemm_lstm_fused(const __nv_bfloat16* __restrict__ xhi, const __nv_bfloat16* __restrict__ xlo,
                     const __nv_bfloat16* __restrict__ hhi, const __nv_bfloat16* __restrict__ hlo,
                     const __nv_bfloat16* __restrict__ wxh, const __nv_bfloat16* __restrict__ wxl,
                     const __nv_bfloat16* __restrict__ whh, const __nv_bfloat16* __restrict__ whl,
                     const float* __restrict__ bsum,
                     float* __restrict__ c,
                     __nv_bfloat16* __restrict__ hhi_w, __nv_bfloat16* __restrict__ hlo_w,
                     float* __restrict__ hlast)
{
    extern __shared__ __align__(1024) char smem_raw[];
    const uint32_t sbase = smem_u32(smem_raw);

    const int tid = threadIdx.x;
    const int wid = tid >> 5;
    const int lane = tid & 31;
    const int wm = wid & 1;          // 2 warps along M (64 rows each)
    const int wn = wid >> 1;         // 4 warps along N (32 cols each)
    const int bn = blockIdx.x * TILE_N;
    const int bm = blockIdx.y * TILE_M;

    auto get_src = [&](int cc, const __nv_bfloat16*& a, const __nv_bfloat16*& b,
                       int& k0, int& kst) {
        const int prod = cc / 24;      // 0: hi*hi, 1: hi*lo, 2: lo*hi
        const int r = cc - prod * 24;
        if (r < 8) {                   // x-part, K=512
            kst = INPUT_D; k0 = r * CHUNK_K;
            a = (prod == 2) ? xlo : xhi;
            b = (prod == 1) ? wxl : wxh;
        } else {                       // h-part, K=1024
            kst = HID; k0 = (r - 8) * CHUNK_K;
            a = (prod == 2) ? hlo : hhi;
            b = (prod == 1) ? whl : whh;
        }
    };

    const int lrow = tid >> 3;            // 0..31
    const int lcol = (tid & 7) * 16;      // 16B block within 128B row
    auto load_chunk = [&](int cc, int stage) {
        const __nv_bfloat16 *a, *b; int k0, kst;
        get_src(cc, a, b, k0, kst);
        const uint32_t abase = sbase + stage * STAGE_BYTES;
        const uint32_t bbase = abase + A_BYTES;
#pragma unroll
        for (int v = 0; v < 4; v++) {
            const int row = v * 32 + lrow;
            cp16(abase + sw128(row * 128 + lcol),
                 a + (size_t)(bm + row) * kst + k0 + lcol / 2);
            cp16(bbase + sw128(row * 128 + lcol),
                 b + (size_t)(bn + row) * kst + k0 + lcol / 2);
        }
    };

    float acc[4][4][4];
#pragma unroll
    for (int i = 0; i < 4; i++)
#pragma unroll
        for (int j = 0; j < 4; j++)
#pragma unroll
            for (int q = 0; q < 4; q++) acc[i][j][q] = 0.0f;

    auto compute_chunk = [&](int stage) {
        const uint32_t abase = sbase + stage * STAGE_BYTES;
        const uint32_t bbase = abase + A_BYTES;
#pragma unroll
        for (int ks = 0; ks < 4; ks++) {
            uint32_t bf[4][2];
#pragma unroll
            for (int ntp = 0; ntp < 2; ntp++) {
                const int g = lane >> 3, l7 = lane & 7;
                const int nrow = wn * 32 + ntp * 16 + ((g >> 1) << 3) + l7;
                const uint32_t addr = bbase + sw128(nrow * 128 + ks * 32 + (g & 1) * 16);
                asm volatile("ldmatrix.sync.aligned.m8n8.x4.shared.b16 {%0,%1,%2,%3}, [%4];"
                    : "=r"(bf[ntp * 2][0]), "=r"(bf[ntp * 2][1]),
                      "=r"(bf[ntp * 2 + 1][0]), "=r"(bf[ntp * 2 + 1][1])
                    : "r"(addr));
            }
#pragma unroll
            for (int mt = 0; mt < 4; mt++) {
                const int mrow = wm * 64 + mt * 16 + (lane & 15);
                const uint32_t aaddr = abase + sw128(mrow * 128 + ks * 32 + (lane >> 4) * 16);
                uint32_t a0, a1, a2, a3;
                asm volatile("ldmatrix.sync.aligned.m8n8.x4.shared.b16 {%0,%1,%2,%3}, [%4];"
                    : "=r"(a0), "=r"(a1), "=r"(a2), "=r"(a3) : "r"(aaddr));
#pragma unroll
                for (int nt = 0; nt < 4; nt++) {
                    asm volatile(
                        "mma.sync.aligned.m16n8k16.row.col.f32.bf16.bf16.f32 "
                        "{%0,%1,%2,%3}, {%4,%5,%6,%7}, {%8,%9}, {%0,%1,%2,%3};"
                        : "+f"(acc[mt][nt][0]), "+f"(acc[mt][nt][1]),
                          "+f"(acc[mt][nt][2]), "+f"(acc[mt][nt][3])
                        : "r"(a0), "r"(a1), "r"(a2), "r"(a3),
                          "r"(bf[nt][0]), "r"(bf[nt][1]));
                }
            }
        }
    };

    // prologue
#pragma unroll
    for (int p = 0; p < NS - 1; p++) { load_chunk(p, p); CP_COMMIT(); }

#pragma unroll 1
    for (int i = 0; i < NCHUNKS; i++) {
        CP_WAIT(NS - 2);
        __syncthreads();
        if (i + NS - 1 < NCHUNKS) load_chunk(i + NS - 1, (i + NS - 1) % NS);
        CP_COMMIT();
        compute_chunk(i % NS);
    }

    // ---------------- epilogue: stage gates in smem, coalesced cell math -----
    CP_WAIT(0);
    __syncthreads();                 // pipeline smem now dead; reuse for gates
    float* sg = reinterpret_cast<float*>(smem_raw);   // [128][EROW]

    // scatter accumulators (registers -> smem, conflicts <= 2-way)
#pragma unroll
    for (int mt = 0; mt < 4; mt++) {
        const int r0 = wm * 64 + mt * 16 + (lane >> 2);
        const int nl = wn * 32 + (lane & 3) * 2;
#pragma unroll
        for (int nt = 0; nt < 4; nt++) {
            float* p0 = sg + r0 * EROW + nl + nt * 8;
            float* p1 = sg + (r0 + 8) * EROW + nl + nt * 8;
            p0[0] = acc[mt][nt][0]; p0[1] = acc[mt][nt][1];
            p1[0] = acc[mt][nt][2]; p1[1] = acc[mt][nt][3];
        }
    }
    __syncthreads();

    // cell phase: warp = one m row, lane = one unit -> coalesced gmem
    const int ubase = bn >> 2;       // first unit of this tile (32 units/tile)
#pragma unroll
    for (int it = 0; it < 16; it++) {
        const int idx = it * 256 + tid;          // 0..4095
        const int ml = idx >> 5;                 // 0..127
        const int ul = idx & 31;                 // 0..31
        const float4 g4 = *reinterpret_cast<const float4*>(sg + ml * EROW + ul * 4);
        const float4 b4 = *reinterpret_cast<const float4*>(bsum + (ubase + ul) * 4);

        const float gi = g4.x + b4.x;
        const float gf = g4.y + b4.y;
        const float gg = g4.z + b4.z;
        const float go = g4.w + b4.w;

        const int m = bm + ml;
        const int u = ubase + ul;
        const int gix = m * HID + u;

        const float co = c[gix];
        const float si = 1.0f / (1.0f + expf(-gi));
        const float sf = 1.0f / (1.0f + expf(-gf));
        const float so = 1.0f / (1.0f + expf(-go));
        const float tg = tanhf(gg);
        const float cn = sf * co + si * tg;
        const float hn = so * tanhf(cn);
        c[gix] = cn;
        const __nv_bfloat16 hh = __float2bfloat16(hn);
        hhi_w[gix] = hh;
        hlo_w[gix] = __float2bfloat16(hn - __bfloat162float(hh));
        if (hlast != nullptr && m == SEQ - 1) hlast[u] = hn;
    }
}

// ---------------- setup kernels ----------------
__global__ void split_kernel(const float* __restrict__ src, __nv_bfloat16* __restrict__ hi,
                             __nv_bfloat16* __restrict__ lo, size_t n, float scale)
{
    const size_t i = (size_t)blockIdx.x * blockDim.x + threadIdx.x;
    if (i < n) {
        const float v = src[i] * scale;
        const __nv_bfloat16 h = __float2bfloat16(v);
        hi[i] = h;
        lo[i] = __float2bfloat16(v - __bfloat162float(h));
    }
}

// permute rows to gate-interleaved order: new_row = 4*unit + gate
__global__ void split_permute_w(const float* __restrict__ src, __nv_bfloat16* __restrict__ hi,
                                __nv_bfloat16* __restrict__ lo, int kshift)
{
    const size_t i = (size_t)blockIdx.x * blockDim.x + threadIdx.x;
    const int K = 1 << kshift;
    if (i < (size_t)GATES_N << kshift) {
        const int row = (int)(i >> kshift);
        const int k = (int)(i & (K - 1));
        const int nrow = ((row & 1023) << 2) | (row >> 10);
        const float v = src[i];
        const __nv_bfloat16 h = __float2bfloat16(v);
        hi[(size_t)nrow * K + k] = h;
        lo[(size_t)nrow * K + k] = __float2bfloat16(v - __bfloat162float(h));
    }
}

__global__ void bias_combine(const float* __restrict__ b_ih, const float* __restrict__ b_hh,
                             float* __restrict__ bsum)
{
    const int i = blockIdx.x * blockDim.x + threadIdx.x;
    if (i < GATES_N) {
        const int ni = ((i & 1023) << 2) | (i >> 10);
        bsum[ni] = b_ih[i] + b_hh[i];
    }
}

__global__ void zero_state_kernel()
{
    const int i = blockIdx.x * blockDim.x + threadIdx.x;
    if (i < SEQ * HID) {
        g_hhi[0][i] = __float2bfloat16(0.f);
        g_hlo[0][i] = __float2bfloat16(0.f);
        g_hhi[1][i] = __float2bfloat16(0.f);
        g_hlo[1][i] = __float2bfloat16(0.f);
        g_c[i] = 0.f;
    }
}

__global__ __launch_bounds__(256)
void fc_kernel(const float* __restrict__ Hl, const float* __restrict__ Wfc,
               const float* __restrict__ bfc, float* __restrict__ out)
{
    __shared__ float hrow[HID];
    const int t = blockIdx.x;
    for (int k = threadIdx.x; k < HID; k += 256) hrow[k] = Hl[(size_t)t * HID + k];
    __syncthreads();
    for (int n = threadIdx.x; n < OUT_D; n += 256) {
        const float* w = Wfc + (size_t)n * HID;
        float s = 0.f;
#pragma unroll 8
        for (int k = 0; k < HID; k++) s = fmaf(hrow[k], w[k], s);
        out[(size_t)t * OUT_D + n] = s + bfc[n];
    }
}

// ---------------- launch ----------------
extern "C" void kernel_launch(void* const* d_in, const int* in_sizes, int n_in,
                              void* d_out, int out_size)
{
    const float* x     = (const float*)d_in[0];
    const float* w_ih1 = (const float*)d_in[1];
    const float* w_hh1 = (const float*)d_in[2];
    const float* b_ih1 = (const float*)d_in[3];
    const float* b_hh1 = (const float*)d_in[4];
    const float* w_ih2 = (const float*)d_in[5];
    const float* w_hh2 = (const float*)d_in[6];
    const float* b_ih2 = (const float*)d_in[7];
    const float* b_hh2 = (const float*)d_in[8];
    const float* w_fc  = (const float*)d_in[9];
    const float* b_fc  = (const float*)d_in[10];
    float* out = (float*)d_out;

    __nv_bfloat16 *xhi, *xlo, *wxh, *wxl, *whh, *whl, *hhi, *hlo;
    float *c, *hlast, *bias;
    cudaGetSymbolAddress((void**)&xhi, g_xhi);
    cudaGetSymbolAddress((void**)&xlo, g_xlo);
    cudaGetSymbolAddress((void**)&wxh, g_wxh);
    cudaGetSymbolAddress((void**)&wxl, g_wxl);
    cudaGetSymbolAddress((void**)&whh, g_whh);
    cudaGetSymbolAddress((void**)&whl, g_whl);
    cudaGetSymbolAddress((void**)&hhi, g_hhi);
    cudaGetSymbolAddress((void**)&hlo, g_hlo);
    cudaGetSymbolAddress((void**)&c,     g_c);
    cudaGetSymbolAddress((void**)&hlast, g_hlast);
    cudaGetSymbolAddress((void**)&bias,  g_bias);

    cudaFuncSetAttribute(gemm_lstm_fused, cudaFuncAttributeMaxDynamicSharedMemorySize, SMEM_DYN);

    const size_t nwx = (size_t)GATES_N * INPUT_D;
    const size_t nwh = (size_t)GATES_N * HID;

    // setup: split x (*255), permute+split weights, combine+permute biases
    {
        const size_t nx = (size_t)STEPS * SEQ * INPUT_D;
        split_kernel<<<(unsigned)((nx + 255) / 256), 256>>>(x, xhi, xlo, nx, 255.0f);
        split_permute_w<<<(unsigned)((nwx + 255) / 256), 256>>>(w_ih1, wxh, wxl, 9);
        split_permute_w<<<(unsigned)((nwh + 255) / 256), 256>>>(w_hh1, whh, whl, 10);
        split_permute_w<<<(unsigned)((nwx + 255) / 256), 256>>>(w_ih2, wxh + nwx, wxl + nwx, 9);
        split_permute_w<<<(unsigned)((nwh + 255) / 256), 256>>>(w_hh2, whh + nwh, whl + nwh, 10);
        bias_combine<<<(GATES_N + 255) / 256, 256>>>(b_ih1, b_hh1, bias);
        bias_combine<<<(GATES_N + 255) / 256, 256>>>(b_ih2, b_hh2, bias + GATES_N);
    }
    zero_state_kernel<<<(SEQ * HID + 255) / 256, 256>>>();

    const dim3 ggrid(GATES_N / TILE_N, SEQ / TILE_M);   // (32, 8) = 256 CTAs
    int p = 0;
    for (int t = 0; t < STEPS; ++t) {
        const __nv_bfloat16* xth = xhi + (size_t)t * SEQ * INPUT_D;
        const __nv_bfloat16* xtl = xlo + (size_t)t * SEQ * INPUT_D;

        gemm_lstm_fused<<<ggrid, 256, SMEM_DYN>>>(
            xth, xtl, hhi + (size_t)p * SEQ * HID, hlo + (size_t)p * SEQ * HID,
            wxh, wxl, whh, whl, bias, c,
            hhi + (size_t)(1 - p) * SEQ * HID, hlo + (size_t)(1 - p) * SEQ * HID,
            nullptr);
        p ^= 1;

        gemm_lstm_fused<<<ggrid, 256, SMEM_DYN>>>(
            xth, xtl, hhi + (size_t)p * SEQ * HID, hlo + (size_t)p * SEQ * HID,
            wxh + nwx, wxl + nwx, whh + nwh, whl + nwh, bias + GATES_N, c,
            hhi + (size_t)(1 - p) * SEQ * HID, hlo + (size_t)(1 - p) * SEQ * HID,
            hlast + (size_t)t * HID);
        p ^= 1;
    }

    fc_kernel<<<STEPS, 256>>>(hlast, w_fc, b_fc, out);
}

// round 8
// speedup vs baseline: 1.2843x; 1.0155x over previous
#include <cuda_runtime.h>
#include <cuda_bf16.h>
#include <cstdint>
#include <math.h>

#define SEQ     1024
#define INPUT_D 512
#define HID     1024
#define GATES_N 4096
#define STEPS   128
#define OUT_D   1000

// ---------------- device scratch (no cudaMalloc allowed) ----------------
__device__ __nv_bfloat16 g_xhi[(size_t)STEPS * SEQ * INPUT_D];
__device__ __nv_bfloat16 g_xlo[(size_t)STEPS * SEQ * INPUT_D];
__device__ __nv_bfloat16 g_wxh[2][GATES_N * INPUT_D];
__device__ __nv_bfloat16 g_wxl[2][GATES_N * INPUT_D];
__device__ __nv_bfloat16 g_whh[2][GATES_N * HID];
__device__ __nv_bfloat16 g_whl[2][GATES_N * HID];
__device__ __nv_bfloat16 g_hhi[SEQ * HID];
__device__ __nv_bfloat16 g_hlo[SEQ * HID];
__device__ float g_c[SEQ * HID];
__device__ float g_gates[2][(size_t)SEQ * GATES_N];   // split-K partial sums
__device__ float g_hlast[STEPS * HID];

// ---------------- helpers ----------------
__device__ __forceinline__ uint32_t smem_u32(const void* p) {
    return (uint32_t)__cvta_generic_to_shared(p);
}
__device__ __forceinline__ void cp16(uint32_t saddr, const void* gaddr) {
    asm volatile("cp.async.cg.shared.global [%0], [%1], 16;" :: "r"(saddr), "l"(gaddr) : "memory");
}
#define CP_COMMIT() asm volatile("cp.async.commit_group;" ::: "memory")
#define CP_WAIT(n)  asm volatile("cp.async.wait_group %0;" :: "n"(n) : "memory")

__device__ __forceinline__ uint32_t sw128(uint32_t off) {
    return off ^ ((off >> 3) & 0x70);
}

// ---------------- GEMM (mma.sync bf16 x3 emulation, split-K=2) ----------------
#define TILE_M   128
#define TILE_N   128
#define CHUNK_K  64
#define NS       3
#define NCHUNKS_TOTAL 72
#define NCH_HALF 36
#define A_BYTES  (TILE_M * CHUNK_K * 2)      // 16 KB
#define STAGE_BYTES (2 * A_BYTES)            // 32 KB
#define SMEM_DYN (NS * STAGE_BYTES)          // 96 KB -> 2 CTAs/SM

__global__ __launch_bounds__(256, 2)
void gemm_half(const __nv_bfloat16* __restrict__ xhi, const __nv_bfloat16* __restrict__ xlo,
               const __nv_bfloat16* __restrict__ hhi, const __nv_bfloat16* __restrict__ hlo,
               const __nv_bfloat16* __restrict__ wxh, const __nv_bfloat16* __restrict__ wxl,
               const __nv_bfloat16* __restrict__ whh, const __nv_bfloat16* __restrict__ whl,
               float* __restrict__ gpart)   // [2][SEQ][GATES_N]
{
    extern __shared__ __align__(1024) char smem_raw[];
    const uint32_t sbase = smem_u32(smem_raw);

    const int tid = threadIdx.x;
    const int wid = tid >> 5;
    const int lane = tid & 31;
    const int wm = wid & 1;          // 2 warps along M
    const int wn = wid >> 1;         // 4 warps along N
    const int bn = blockIdx.x * TILE_N;
    const int bm = blockIdx.y * TILE_M;
    const int kh = blockIdx.z;       // K-half: chunks [kh*36, kh*36+36)
    const int cbase = kh * NCH_HALF;
    float* out = gpart + (size_t)kh * SEQ * GATES_N;

    auto get_src = [&](int cc, const __nv_bfloat16*& a, const __nv_bfloat16*& b,
                       int& k0, int& kst) {
        const int prod = cc / 24;      // 0: hi*hi, 1: hi*lo, 2: lo*hi
        const int r = cc - prod * 24;
        if (r < 8) {                   // x-part, K=512
            kst = INPUT_D; k0 = r * CHUNK_K;
            a = (prod == 2) ? xlo : xhi;
            b = (prod == 1) ? wxl : wxh;
        } else {                       // h-part, K=1024
            kst = HID; k0 = (r - 8) * CHUNK_K;
            a = (prod == 2) ? hlo : hhi;
            b = (prod == 1) ? whl : whh;
        }
    };

    const int lrow = tid >> 3;
    const int lcol = (tid & 7) * 16;
    auto load_chunk = [&](int ci, int stage) {
        const __nv_bfloat16 *a, *b; int k0, kst;
        get_src(cbase + ci, a, b, k0, kst);
        const uint32_t abase = sbase + stage * STAGE_BYTES;
        const uint32_t bbase = abase + A_BYTES;
#pragma unroll
        for (int v = 0; v < 4; v++) {
            const int row = v * 32 + lrow;
            cp16(abase + sw128(row * 128 + lcol),
                 a + (size_t)(bm + row) * kst + k0 + lcol / 2);
            cp16(bbase + sw128(row * 128 + lcol),
                 b + (size_t)(bn + row) * kst + k0 + lcol / 2);
        }
    };

    float acc[4][4][4];
#pragma unroll
    for (int i = 0; i < 4; i++)
#pragma unroll
        for (int j = 0; j < 4; j++)
#pragma unroll
            for (int q = 0; q < 4; q++) acc[i][j][q] = 0.0f;

    auto compute_chunk = [&](int stage) {
        const uint32_t abase = sbase + stage * STAGE_BYTES;
        const uint32_t bbase = abase + A_BYTES;
#pragma unroll
        for (int ks = 0; ks < 4; ks++) {
            uint32_t bf[4][2];
#pragma unroll
            for (int ntp = 0; ntp < 2; ntp++) {
                const int g = lane >> 3, l7 = lane & 7;
                const int nrow = wn * 32 + ntp * 16 + ((g >> 1) << 3) + l7;
                const uint32_t addr = bbase + sw128(nrow * 128 + ks * 32 + (g & 1) * 16);
                asm volatile("ldmatrix.sync.aligned.m8n8.x4.shared.b16 {%0,%1,%2,%3}, [%4];"
                    : "=r"(bf[ntp * 2][0]), "=r"(bf[ntp * 2][1]),
                      "=r"(bf[ntp * 2 + 1][0]), "=r"(bf[ntp * 2 + 1][1])
                    : "r"(addr));
            }
            // A-fragment prefetch pipeline across mt
            const int arow_l = lane & 15;
            const int acol_l = (lane >> 4) * 16;
            uint32_t acur[4], anxt[4];
            {
                const int mrow = wm * 64 + 0 * 16 + arow_l;
                const uint32_t aaddr = abase + sw128(mrow * 128 + ks * 32 + acol_l);
                asm volatile("ldmatrix.sync.aligned.m8n8.x4.shared.b16 {%0,%1,%2,%3}, [%4];"
                    : "=r"(acur[0]), "=r"(acur[1]), "=r"(acur[2]), "=r"(acur[3]) : "r"(aaddr));
            }
#pragma unroll
            for (int mt = 0; mt < 4; mt++) {
                if (mt < 3) {
                    const int mrow = wm * 64 + (mt + 1) * 16 + arow_l;
                    const uint32_t aaddr = abase + sw128(mrow * 128 + ks * 32 + acol_l);
                    asm volatile("ldmatrix.sync.aligned.m8n8.x4.shared.b16 {%0,%1,%2,%3}, [%4];"
                        : "=r"(anxt[0]), "=r"(anxt[1]), "=r"(anxt[2]), "=r"(anxt[3]) : "r"(aaddr));
                }
#pragma unroll
                for (int nt = 0; nt < 4; nt++) {
                    asm volatile(
                        "mma.sync.aligned.m16n8k16.row.col.f32.bf16.bf16.f32 "
                        "{%0,%1,%2,%3}, {%4,%5,%6,%7}, {%8,%9}, {%0,%1,%2,%3};"
                        : "+f"(acc[mt][nt][0]), "+f"(acc[mt][nt][1]),
                          "+f"(acc[mt][nt][2]), "+f"(acc[mt][nt][3])
                        : "r"(acur[0]), "r"(acur[1]), "r"(acur[2]), "r"(acur[3]),
                          "r"(bf[nt][0]), "r"(bf[nt][1]));
                }
#pragma unroll
                for (int q = 0; q < 4; q++) acur[q] = anxt[q];
            }
        }
    };

    // prologue
#pragma unroll
    for (int p = 0; p < NS - 1; p++) { load_chunk(p, p); CP_COMMIT(); }

#pragma unroll 1
    for (int i = 0; i < NCH_HALF; i++) {
        CP_WAIT(NS - 2);
        __syncthreads();
        if (i + NS - 1 < NCH_HALF) load_chunk(i + NS - 1, (i + NS - 1) % NS);
        CP_COMMIT();
        compute_chunk(i % NS);
    }

    // epilogue: raw partial sums (bias added in cell kernel)
#pragma unroll
    for (int mt = 0; mt < 4; mt++) {
        const int m0 = bm + wm * 64 + mt * 16 + (lane >> 2);
#pragma unroll
        for (int nt = 0; nt < 4; nt++) {
            const int n0 = bn + wn * 32 + nt * 8 + (lane & 3) * 2;
            float2 v0, v1;
            v0.x = acc[mt][nt][0]; v0.y = acc[mt][nt][1];
            v1.x = acc[mt][nt][2]; v1.y = acc[mt][nt][3];
            *reinterpret_cast<float2*>(out + (size_t)m0 * GATES_N + n0) = v0;
            *reinterpret_cast<float2*>(out + (size_t)(m0 + 8) * GATES_N + n0) = v1;
        }
    }
}

// ---------------- pointwise kernels ----------------
__global__ void split_kernel(const float* __restrict__ src, __nv_bfloat16* __restrict__ hi,
                             __nv_bfloat16* __restrict__ lo, size_t n, float scale)
{
    const size_t i = (size_t)blockIdx.x * blockDim.x + threadIdx.x;
    if (i < n) {
        const float v = src[i] * scale;
        const __nv_bfloat16 h = __float2bfloat16(v);
        hi[i] = h;
        lo[i] = __float2bfloat16(v - __bfloat162float(h));
    }
}

__global__ void zero_state_kernel()
{
    const int i = blockIdx.x * blockDim.x + threadIdx.x;
    if (i < SEQ * HID) {
        g_hhi[i] = __float2bfloat16(0.f);
        g_hlo[i] = __float2bfloat16(0.f);
        g_c[i] = 0.f;
    }
}

__global__ __launch_bounds__(256)
void lstm_cell_kernel(const float* __restrict__ g0, const float* __restrict__ g1,
                      const float* __restrict__ b_ih, const float* __restrict__ b_hh,
                      __nv_bfloat16* __restrict__ hhi, __nv_bfloat16* __restrict__ hlo,
                      float* __restrict__ c, float* __restrict__ hlast)
{
    const int idx = blockIdx.x * blockDim.x + threadIdx.x;
    const int m = idx >> 10;
    const int j = idx & 1023;
    const size_t ro = (size_t)m * GATES_N;

    const float gi = g0[ro + j]            + g1[ro + j]            + b_ih[j]            + b_hh[j];
    const float gf = g0[ro + j + HID]      + g1[ro + j + HID]      + b_ih[j + HID]      + b_hh[j + HID];
    const float gg = g0[ro + j + 2 * HID]  + g1[ro + j + 2 * HID]  + b_ih[j + 2 * HID]  + b_hh[j + 2 * HID];
    const float go = g0[ro + j + 3 * HID]  + g1[ro + j + 3 * HID]  + b_ih[j + 3 * HID]  + b_hh[j + 3 * HID];

    const float si = 1.0f / (1.0f + expf(-gi));
    const float sf = 1.0f / (1.0f + expf(-gf));
    const float so = 1.0f / (1.0f + expf(-go));
    const float tg = tanhf(gg);

    const float cn = sf * c[idx] + si * tg;
    const float hn = so * tanhf(cn);
    c[idx] = cn;

    const __nv_bfloat16 hh = __float2bfloat16(hn);
    hhi[idx] = hh;
    hlo[idx] = __float2bfloat16(hn - __bfloat162float(hh));
    if (hlast != nullptr && m == SEQ - 1) hlast[j] = hn;
}

__global__ __launch_bounds__(256)
void fc_kernel(const float* __restrict__ Hl, const float* __restrict__ Wfc,
               const float* __restrict__ bfc, float* __restrict__ out)
{
    __shared__ float hrow[HID];
    const int t = blockIdx.x;
    for (int k = threadIdx.x; k < HID; k += 256) hrow[k] = Hl[(size_t)t * HID + k];
    __syncthreads();
    for (int n = threadIdx.x; n < OUT_D; n += 256) {
        const float* w = Wfc + (size_t)n * HID;
        float s = 0.f;
#pragma unroll 8
        for (int k = 0; k < HID; k++) s = fmaf(hrow[k], w[k], s);
        out[(size_t)t * OUT_D + n] = s + bfc[n];
    }
}

// ---------------- launch ----------------
extern "C" void kernel_launch(void* const* d_in, const int* in_sizes, int n_in,
                              void* d_out, int out_size)
{
    const float* x     = (const float*)d_in[0];
    const float* w_ih1 = (const float*)d_in[1];
    const float* w_hh1 = (const float*)d_in[2];
    const float* b_ih1 = (const float*)d_in[3];
    const float* b_hh1 = (const float*)d_in[4];
    const float* w_ih2 = (const float*)d_in[5];
    const float* w_hh2 = (const float*)d_in[6];
    const float* b_ih2 = (const float*)d_in[7];
    const float* b_hh2 = (const float*)d_in[8];
    const float* w_fc  = (const float*)d_in[9];
    const float* b_fc  = (const float*)d_in[10];
    float* out = (float*)d_out;

    __nv_bfloat16 *xhi, *xlo, *wxh, *wxl, *whh, *whl, *hhi, *hlo;
    float *c, *gates, *hlast;
    cudaGetSymbolAddress((void**)&xhi, g_xhi);
    cudaGetSymbolAddress((void**)&xlo, g_xlo);
    cudaGetSymbolAddress((void**)&wxh, g_wxh);
    cudaGetSymbolAddress((void**)&wxl, g_wxl);
    cudaGetSymbolAddress((void**)&whh, g_whh);
    cudaGetSymbolAddress((void**)&whl, g_whl);
    cudaGetSymbolAddress((void**)&hhi, g_hhi);
    cudaGetSymbolAddress((void**)&hlo, g_hlo);
    cudaGetSymbolAddress((void**)&c,     g_c);
    cudaGetSymbolAddress((void**)&gates, g_gates);
    cudaGetSymbolAddress((void**)&hlast, g_hlast);

    cudaFuncSetAttribute(gemm_half, cudaFuncAttributeMaxDynamicSharedMemorySize, SMEM_DYN);

    const size_t nwx = (size_t)GATES_N * INPUT_D;
    const size_t nwh = (size_t)GATES_N * HID;

    // setup: split x (*255) and weights into bf16 hi/lo
    {
        const size_t nx = (size_t)STEPS * SEQ * INPUT_D;
        split_kernel<<<(unsigned)((nx + 255) / 256), 256>>>(x, xhi, xlo, nx, 255.0f);
        split_kernel<<<(unsigned)((nwx + 255) / 256), 256>>>(w_ih1, wxh, wxl, nwx, 1.0f);
        split_kernel<<<(unsigned)((nwh + 255) / 256), 256>>>(w_hh1, whh, whl, nwh, 1.0f);
        split_kernel<<<(unsigned)((nwx + 255) / 256), 256>>>(w_ih2, wxh + nwx, wxl + nwx, nwx, 1.0f);
        split_kernel<<<(unsigned)((nwh + 255) / 256), 256>>>(w_hh2, whh + nwh, whl + nwh, nwh, 1.0f);
    }
    zero_state_kernel<<<(SEQ * HID + 255) / 256, 256>>>();

    const dim3 ggrid(GATES_N / TILE_N, SEQ / TILE_M, 2);   // (32, 8, 2) = 512 CTAs
    const int cell_blocks = (SEQ * HID) / 256;

    for (int t = 0; t < STEPS; ++t) {
        const __nv_bfloat16* xth = xhi + (size_t)t * SEQ * INPUT_D;
        const __nv_bfloat16* xtl = xlo + (size_t)t * SEQ * INPUT_D;

        gemm_half<<<ggrid, 256, SMEM_DYN>>>(xth, xtl, hhi, hlo,
                                            wxh, wxl, whh, whl, gates);
        lstm_cell_kernel<<<cell_blocks, 256>>>(gates, gates + (size_t)SEQ * GATES_N,
                                               b_ih1, b_hh1, hhi, hlo, c, nullptr);

        gemm_half<<<ggrid, 256, SMEM_DYN>>>(xth, xtl, hhi, hlo,
                                            wxh + nwx, wxl + nwx, whh + nwh, whl + nwh, gates);
        lstm_cell_kernel<<<cell_blocks, 256>>>(gates, gates + (size_t)SEQ * GATES_N,
                                               b_ih2, b_hh2, hhi, hlo, c,
                                               hlast + (size_t)t * HID);
    }

    fc_kernel<<<STEPS, 256>>>(hlast, w_fc, b_fc, out);
}

// round 9
// speedup vs baseline: 1.3237x; 1.0307x over previous
#include <cuda_runtime.h>
#include <cuda_bf16.h>
#include <cstdint>
#include <math.h>

#define SEQ     1024
#define INPUT_D 512
#define HID     1024
#define GATES_N 4096
#define STEPS   128
#define OUT_D   1000

// ---------------- device scratch (no cudaMalloc allowed) ----------------
__device__ __nv_bfloat16 g_xhi[(size_t)STEPS * SEQ * INPUT_D];
__device__ __nv_bfloat16 g_xlo[(size_t)STEPS * SEQ * INPUT_D];
__device__ __nv_bfloat16 g_wxh[2][GATES_N * INPUT_D];
__device__ __nv_bfloat16 g_wxl[2][GATES_N * INPUT_D];
__device__ __nv_bfloat16 g_whh[2][GATES_N * HID];
__device__ __nv_bfloat16 g_whl[2][GATES_N * HID];
__device__ __nv_bfloat16 g_hhi[SEQ * HID];
__device__ __nv_bfloat16 g_hlo[SEQ * HID];
__device__ float g_c[SEQ * HID];
__device__ float g_gates[(size_t)SEQ * GATES_N];
__device__ float g_hlast[STEPS * HID];

// ---------------- helpers ----------------
__device__ __forceinline__ uint32_t smem_u32(const void* p) {
    return (uint32_t)__cvta_generic_to_shared(p);
}
__device__ __forceinline__ void cp16(uint32_t saddr, const void* gaddr) {
    asm volatile("cp.async.cg.shared.global [%0], [%1], 16;" :: "r"(saddr), "l"(gaddr) : "memory");
}
#define CP_COMMIT() asm volatile("cp.async.commit_group;" ::: "memory")
#define CP_WAIT(n)  asm volatile("cp.async.wait_group %0;" :: "n"(n) : "memory")

__device__ __forceinline__ uint32_t sw128(uint32_t off) {
    return off ^ ((off >> 3) & 0x70);
}

// ---------------- GEMM (mma.sync bf16 x3 emulation, x-chunks first + PDL) ----
#define TILE_M   128
#define TILE_N   128
#define CHUNK_K  64
#define NS       3
#define NCHUNKS  72
#define FIRST_H  24                          // chunks [0,24) = x-part (no h dep)
#define A_BYTES  (TILE_M * CHUNK_K * 2)      // 16 KB
#define STAGE_BYTES (2 * A_BYTES)            // 32 KB
#define SMEM_DYN (NS * STAGE_BYTES)          // 96 KB -> 2 CTAs/SM

__global__ __launch_bounds__(256, 2)
void gemm_gates(const __nv_bfloat16* __restrict__ xhi, const __nv_bfloat16* __restrict__ xlo,
                const __nv_bfloat16* __restrict__ hhi, const __nv_bfloat16* __restrict__ hlo,
                const __nv_bfloat16* __restrict__ wxh, const __nv_bfloat16* __restrict__ wxl,
                const __nv_bfloat16* __restrict__ whh, const __nv_bfloat16* __restrict__ whl,
                const float* __restrict__ b1, const float* __restrict__ b2,
                float* __restrict__ out)
{
    extern __shared__ __align__(1024) char smem_raw[];
    const uint32_t sbase = smem_u32(smem_raw);

    const int tid = threadIdx.x;
    const int wid = tid >> 5;
    const int lane = tid & 31;
    const int wm = wid & 1;          // 2 warps along M
    const int wn = wid >> 1;         // 4 warps along N
    const int bn = blockIdx.x * TILE_N;
    const int bm = blockIdx.y * TILE_M;

    // chunk order: 24 x-chunks (3 products x 8), then 48 h-chunks (3 x 16)
    auto get_src = [&](int cc, const __nv_bfloat16*& a, const __nv_bfloat16*& b,
                       int& k0, int& kst) {
        if (cc < FIRST_H) {            // x-part, K=512
            const int prod = cc >> 3;
            kst = INPUT_D; k0 = (cc & 7) * CHUNK_K;
            a = (prod == 2) ? xlo : xhi;
            b = (prod == 1) ? wxl : wxh;
        } else {                       // h-part, K=1024
            const int q = cc - FIRST_H;
            const int prod = q >> 4;
            kst = HID; k0 = (q & 15) * CHUNK_K;
            a = (prod == 2) ? hlo : hhi;
            b = (prod == 1) ? whl : whh;
        }
    };

    const int lrow = tid >> 3;
    const int lcol = (tid & 7) * 16;
    auto load_chunk = [&](int cc, int stage) {
        const __nv_bfloat16 *a, *b; int k0, kst;
        get_src(cc, a, b, k0, kst);
        const uint32_t abase = sbase + stage * STAGE_BYTES;
        const uint32_t bbase = abase + A_BYTES;
#pragma unroll
        for (int v = 0; v < 4; v++) {
            const int row = v * 32 + lrow;
            cp16(abase + sw128(row * 128 + lcol),
                 a + (size_t)(bm + row) * kst + k0 + lcol / 2);
            cp16(bbase + sw128(row * 128 + lcol),
                 b + (size_t)(bn + row) * kst + k0 + lcol / 2);
        }
    };

    float acc[4][4][4];
#pragma unroll
    for (int i = 0; i < 4; i++)
#pragma unroll
        for (int j = 0; j < 4; j++)
#pragma unroll
            for (int q = 0; q < 4; q++) acc[i][j][q] = 0.0f;

    auto compute_chunk = [&](int stage) {
        const uint32_t abase = sbase + stage * STAGE_BYTES;
        const uint32_t bbase = abase + A_BYTES;
#pragma unroll
        for (int ks = 0; ks < 4; ks++) {
            uint32_t bf[4][2];
#pragma unroll
            for (int ntp = 0; ntp < 2; ntp++) {
                const int g = lane >> 3, l7 = lane & 7;
                const int nrow = wn * 32 + ntp * 16 + ((g >> 1) << 3) + l7;
                const uint32_t addr = bbase + sw128(nrow * 128 + ks * 32 + (g & 1) * 16);
                asm volatile("ldmatrix.sync.aligned.m8n8.x4.shared.b16 {%0,%1,%2,%3}, [%4];"
                    : "=r"(bf[ntp * 2][0]), "=r"(bf[ntp * 2][1]),
                      "=r"(bf[ntp * 2 + 1][0]), "=r"(bf[ntp * 2 + 1][1])
                    : "r"(addr));
            }
            // A-fragment prefetch pipeline across mt
            const int arow_l = lane & 15;
            const int acol_l = (lane >> 4) * 16;
            uint32_t acur[4], anxt[4];
            {
                const int mrow = wm * 64 + arow_l;
                const uint32_t aaddr = abase + sw128(mrow * 128 + ks * 32 + acol_l);
                asm volatile("ldmatrix.sync.aligned.m8n8.x4.shared.b16 {%0,%1,%2,%3}, [%4];"
                    : "=r"(acur[0]), "=r"(acur[1]), "=r"(acur[2]), "=r"(acur[3]) : "r"(aaddr));
            }
#pragma unroll
            for (int mt = 0; mt < 4; mt++) {
                if (mt < 3) {
                    const int mrow = wm * 64 + (mt + 1) * 16 + arow_l;
                    const uint32_t aaddr = abase + sw128(mrow * 128 + ks * 32 + acol_l);
                    asm volatile("ldmatrix.sync.aligned.m8n8.x4.shared.b16 {%0,%1,%2,%3}, [%4];"
                        : "=r"(anxt[0]), "=r"(anxt[1]), "=r"(anxt[2]), "=r"(anxt[3]) : "r"(aaddr));
                }
#pragma unroll
                for (int nt = 0; nt < 4; nt++) {
                    asm volatile(
                        "mma.sync.aligned.m16n8k16.row.col.f32.bf16.bf16.f32 "
                        "{%0,%1,%2,%3}, {%4,%5,%6,%7}, {%8,%9}, {%0,%1,%2,%3};"
                        : "+f"(acc[mt][nt][0]), "+f"(acc[mt][nt][1]),
                          "+f"(acc[mt][nt][2]), "+f"(acc[mt][nt][3])
                        : "r"(acur[0]), "r"(acur[1]), "r"(acur[2]), "r"(acur[3]),
                          "r"(bf[nt][0]), "r"(bf[nt][1]));
                }
#pragma unroll
                for (int q = 0; q < 4; q++) acur[q] = anxt[q];
            }
        }
    };

    // prologue (x chunks only -> no dependency on upstream kernel)
#pragma unroll
    for (int p = 0; p < NS - 1; p++) { load_chunk(p, p); CP_COMMIT(); }

#pragma unroll 1
    for (int i = 0; i < NCHUNKS; i++) {
        CP_WAIT(NS - 2);
        __syncthreads();
        const int nc = i + NS - 1;
        if (nc < NCHUNKS) {
            if (nc == FIRST_H)
                cudaGridDependencySynchronize();   // h now final (upstream cell done)
            load_chunk(nc, nc % NS);
        }
        CP_COMMIT();
        compute_chunk(i % NS);
    }

    // epilogue: add biases, write gates
#pragma unroll
    for (int mt = 0; mt < 4; mt++) {
        const int m0 = bm + wm * 64 + mt * 16 + (lane >> 2);
#pragma unroll
        for (int nt = 0; nt < 4; nt++) {
            const int n0 = bn + wn * 32 + nt * 8 + (lane & 3) * 2;
            const float bs0 = b1[n0] + b2[n0];
            const float bs1 = b1[n0 + 1] + b2[n0 + 1];
            float2 v0, v1;
            v0.x = acc[mt][nt][0] + bs0; v0.y = acc[mt][nt][1] + bs1;
            v1.x = acc[mt][nt][2] + bs0; v1.y = acc[mt][nt][3] + bs1;
            *reinterpret_cast<float2*>(out + (size_t)m0 * GATES_N + n0) = v0;
            *reinterpret_cast<float2*>(out + (size_t)(m0 + 8) * GATES_N + n0) = v1;
        }
    }
    cudaTriggerProgrammaticLaunchCompletion();
}

// ---------------- pointwise kernels ----------------
__global__ void split_kernel(const float* __restrict__ src, __nv_bfloat16* __restrict__ hi,
                             __nv_bfloat16* __restrict__ lo, size_t n, float scale)
{
    const size_t i = (size_t)blockIdx.x * blockDim.x + threadIdx.x;
    if (i < n) {
        const float v = src[i] * scale;
        const __nv_bfloat16 h = __float2bfloat16(v);
        hi[i] = h;
        lo[i] = __float2bfloat16(v - __bfloat162float(h));
    }
}

__global__ void zero_state_kernel()
{
    const int i = blockIdx.x * blockDim.x + threadIdx.x;
    if (i < SEQ * HID) {
        g_hhi[i] = __float2bfloat16(0.f);
        g_hlo[i] = __float2bfloat16(0.f);
        g_c[i] = 0.f;
    }
}

__global__ __launch_bounds__(256)
void lstm_cell_kernel(const float* __restrict__ gates,
                      __nv_bfloat16* __restrict__ hhi, __nv_bfloat16* __restrict__ hlo,
                      float* __restrict__ c, float* __restrict__ hlast)
{
    cudaGridDependencySynchronize();   // gates must be final
    const int idx = blockIdx.x * blockDim.x + threadIdx.x;
    const int m = idx >> 10;
    const int j = idx & 1023;
    const float* gr = gates + (size_t)m * GATES_N;
    const float gi = gr[j];
    const float gf = gr[j + HID];
    const float gg = gr[j + 2 * HID];
    const float go = gr[j + 3 * HID];

    const float si = 1.0f / (1.0f + expf(-gi));
    const float sf = 1.0f / (1.0f + expf(-gf));
    const float so = 1.0f / (1.0f + expf(-go));
    const float tg = tanhf(gg);

    const float cn = sf * c[idx] + si * tg;
    const float hn = so * tanhf(cn);
    c[idx] = cn;

    const __nv_bfloat16 hh = __float2bfloat16(hn);
    hhi[idx] = hh;
    hlo[idx] = __float2bfloat16(hn - __bfloat162float(hh));
    if (hlast != nullptr && m == SEQ - 1) hlast[j] = hn;
    cudaTriggerProgrammaticLaunchCompletion();
}

__global__ __launch_bounds__(256)
void fc_kernel(const float* __restrict__ Hl, const float* __restrict__ Wfc,
               const float* __restrict__ bfc, float* __restrict__ out)
{
    __shared__ float hrow[HID];
    const int t = blockIdx.x;
    for (int k = threadIdx.x; k < HID; k += 256) hrow[k] = Hl[(size_t)t * HID + k];
    __syncthreads();
    for (int n = threadIdx.x; n < OUT_D; n += 256) {
        const float* w = Wfc + (size_t)n * HID;
        float s = 0.f;
#pragma unroll 8
        for (int k = 0; k < HID; k++) s = fmaf(hrow[k], w[k], s);
        out[(size_t)t * OUT_D + n] = s + bfc[n];
    }
}

// ---------------- launch ----------------
extern "C" void kernel_launch(void* const* d_in, const int* in_sizes, int n_in,
                              void* d_out, int out_size)
{
    const float* x     = (const float*)d_in[0];
    const float* w_ih1 = (const float*)d_in[1];
    const float* w_hh1 = (const float*)d_in[2];
    const float* b_ih1 = (const float*)d_in[3];
    const float* b_hh1 = (const float*)d_in[4];
    const float* w_ih2 = (const float*)d_in[5];
    const float* w_hh2 = (const float*)d_in[6];
    const float* b_ih2 = (const float*)d_in[7];
    const float* b_hh2 = (const float*)d_in[8];
    const float* w_fc  = (const float*)d_in[9];
    const float* b_fc  = (const float*)d_in[10];
    float* out = (float*)d_out;

    __nv_bfloat16 *xhi, *xlo, *wxh, *wxl, *whh, *whl, *hhi, *hlo;
    float *c, *gates, *hlast;
    cudaGetSymbolAddress((void**)&xhi, g_xhi);
    cudaGetSymbolAddress((void**)&xlo, g_xlo);
    cudaGetSymbolAddress((void**)&wxh, g_wxh);
    cudaGetSymbolAddress((void**)&wxl, g_wxl);
    cudaGetSymbolAddress((void**)&whh, g_whh);
    cudaGetSymbolAddress((void**)&whl, g_whl);
    cudaGetSymbolAddress((void**)&hhi, g_hhi);
    cudaGetSymbolAddress((void**)&hlo, g_hlo);
    cudaGetSymbolAddress((void**)&c,     g_c);
    cudaGetSymbolAddress((void**)&gates, g_gates);
    cudaGetSymbolAddress((void**)&hlast, g_hlast);

    cudaFuncSetAttribute(gemm_gates, cudaFuncAttributeMaxDynamicSharedMemorySize, SMEM_DYN);

    const size_t nwx = (size_t)GATES_N * INPUT_D;
    const size_t nwh = (size_t)GATES_N * HID;

    // setup: split x (*255) and weights into bf16 hi/lo
    {
        const size_t nx = (size_t)STEPS * SEQ * INPUT_D;
        split_kernel<<<(unsigned)((nx + 255) / 256), 256>>>(x, xhi, xlo, nx, 255.0f);
        split_kernel<<<(unsigned)((nwx + 255) / 256), 256>>>(w_ih1, wxh, wxl, nwx, 1.0f);
        split_kernel<<<(unsigned)((nwh + 255) / 256), 256>>>(w_hh1, whh, whl, nwh, 1.0f);
        split_kernel<<<(unsigned)((nwx + 255) / 256), 256>>>(w_ih2, wxh + nwx, wxl + nwx, nwx, 1.0f);
        split_kernel<<<(unsigned)((nwh + 255) / 256), 256>>>(w_hh2, whh + nwh, whl + nwh, nwh, 1.0f);
    }
    zero_state_kernel<<<(SEQ * HID + 255) / 256, 256>>>();

    // PDL launch configs
    cudaLaunchAttribute pdl_attr[1];
    pdl_attr[0].id = cudaLaunchAttributeProgrammaticStreamSerialization;
    pdl_attr[0].val.programmaticStreamSerializationAllowed = 1;

    cudaLaunchConfig_t gemm_cfg = {};
    gemm_cfg.gridDim = dim3(GATES_N / TILE_N, SEQ / TILE_M, 1);   // (32, 8)
    gemm_cfg.blockDim = dim3(256, 1, 1);
    gemm_cfg.dynamicSmemBytes = SMEM_DYN;
    gemm_cfg.stream = 0;
    gemm_cfg.attrs = pdl_attr;
    gemm_cfg.numAttrs = 1;

    cudaLaunchConfig_t cell_cfg = {};
    cell_cfg.gridDim = dim3((SEQ * HID) / 256, 1, 1);
    cell_cfg.blockDim = dim3(256, 1, 1);
    cell_cfg.dynamicSmemBytes = 0;
    cell_cfg.stream = 0;
    cell_cfg.attrs = pdl_attr;
    cell_cfg.numAttrs = 1;

    for (int t = 0; t < STEPS; ++t) {
        const __nv_bfloat16* xth = xhi + (size_t)t * SEQ * INPUT_D;
        const __nv_bfloat16* xtl = xlo + (size_t)t * SEQ * INPUT_D;
        float* hl = (float*)nullptr;

        cudaLaunchKernelEx(&gemm_cfg, gemm_gates,
                           xth, xtl,
                           (const __nv_bfloat16*)hhi, (const __nv_bfloat16*)hlo,
                           (const __nv_bfloat16*)wxh, (const __nv_bfloat16*)wxl,
                           (const __nv_bfloat16*)whh, (const __nv_bfloat16*)whl,
                           b_ih1, b_hh1, gates);
        cudaLaunchKernelEx(&cell_cfg, lstm_cell_kernel,
                           (const float*)gates, hhi, hlo, c, hl);

        cudaLaunchKernelEx(&gemm_cfg, gemm_gates,
                           xth, xtl,
                           (const __nv_bfloat16*)hhi, (const __nv_bfloat16*)hlo,
                           (const __nv_bfloat16*)(wxh + nwx), (const __nv_bfloat16*)(wxl + nwx),
                           (const __nv_bfloat16*)(whh + nwh), (const __nv_bfloat16*)(whl + nwh),
                           b_ih2, b_hh2, gates);
        float* hl2 = hlast + (size_t)t * HID;
        cudaLaunchKernelEx(&cell_cfg, lstm_cell_kernel,
                           (const float*)gates, hhi, hlo, c, hl2);
    }

    fc_kernel<<<STEPS, 256>>>(hlast, w_fc, b_fc, out);
}